// round 1
// baseline (speedup 1.0000x reference)
#include <cuda_runtime.h>
#include <mma.h>
#include <cstdint>

using namespace nvcuda;

#define BB 4
#define SS 2048
#define DD 512
#define HH 8
#define HD 64
#define LDS_ 72   // SMEM leading dim (pad 64 -> 72 floats)

// 16 MB scratch for q = x @ Wq (device global: allocation rules forbid cudaMalloc)
__device__ float g_q[(size_t)BB * SS * DD];

// Split an fp32-valued tf32 fragment into hi/lo tf32 parts (3xTF32 trick).
template <class Frag>
__device__ __forceinline__ void tf32_split(Frag& hi, Frag& lo) {
#pragma unroll
    for (int i = 0; i < hi.num_elements; i++) {
        float v = hi.x[i];
        float h = wmma::__float_to_tf32(v);
        hi.x[i] = h;
        lo.x[i] = wmma::__float_to_tf32(v - h);
    }
}

// ---------------------------------------------------------------------------
// Kernel 1: q = x @ Wq     [8192,512] = [8192,512] @ [512,512]
// CTA tile 64x64, 256 threads (8 warps, each warp owns two 16x16 C tiles).
// ---------------------------------------------------------------------------
__global__ __launch_bounds__(256) void qproj_kernel(const float* __restrict__ x,
                                                    const float* __restrict__ w) {
    __shared__ float As[64 * LDS_];
    __shared__ float Bs[64 * LDS_];

    const int tid  = threadIdx.x;
    const int warp = tid >> 5;
    const int tr   = warp >> 1;        // 0..3 : row tile
    const int tcb  = (warp & 1) * 2;   // 0 or 2 : first of two col tiles
    const int bm   = blockIdx.x;       // 0..127
    const int bn   = blockIdx.y;       // 0..7

    wmma::fragment<wmma::accumulator, 16, 16, 8, float> c[2];
    wmma::fill_fragment(c[0], 0.f);
    wmma::fill_fragment(c[1], 0.f);

    const float* xbase = x + (size_t)bm * 64 * DD;

    for (int k0 = 0; k0 < DD; k0 += 64) {
#pragma unroll
        for (int i = tid; i < 1024; i += 256) {
            int r = i >> 4, c4 = (i & 15) << 2;
            *(float4*)(As + r * LDS_ + c4) =
                *(const float4*)(xbase + (size_t)r * DD + k0 + c4);
            *(float4*)(Bs + r * LDS_ + c4) =
                *(const float4*)(w + (size_t)(k0 + r) * DD + bn * 64 + c4);
        }
        __syncthreads();

#pragma unroll
        for (int kk = 0; kk < 64; kk += 8) {
            wmma::fragment<wmma::matrix_a, 16, 16, 8, wmma::precision::tf32, wmma::row_major> ah, al;
            wmma::load_matrix_sync(ah, As + tr * 16 * LDS_ + kk, LDS_);
            tf32_split(ah, al);
#pragma unroll
            for (int t = 0; t < 2; t++) {
                wmma::fragment<wmma::matrix_b, 16, 16, 8, wmma::precision::tf32, wmma::row_major> bh_, bl_;
                wmma::load_matrix_sync(bh_, Bs + kk * LDS_ + (tcb + t) * 16, LDS_);
                tf32_split(bh_, bl_);
                wmma::mma_sync(c[t], ah, bh_, c[t]);
                wmma::mma_sync(c[t], al, bh_, c[t]);
                wmma::mma_sync(c[t], ah, bl_, c[t]);
            }
        }
        __syncthreads();
    }

#pragma unroll
    for (int t = 0; t < 2; t++) {
        float* dst = g_q + ((size_t)(bm * 64 + tr * 16)) * DD + bn * 64 + (tcb + t) * 16;
        wmma::store_matrix_sync(dst, c[t], DD, wmma::mem_row_major);
    }
}

// ---------------------------------------------------------------------------
// Kernel 2: flash attention over g_q, with Q = K = V.
// Grid: (S/64 q-blocks, B*H). CTA: 256 threads, 64x64 tiles, online softmax.
// All matmuls 3xTF32 (fp32-equivalent accuracy).
// ---------------------------------------------------------------------------
__global__ __launch_bounds__(256) void attn_kernel(float* __restrict__ out) {
    extern __shared__ float sm[];
    float* Qs   = sm;                 // 64 x LDS_
    float* Ks   = Qs + 64 * LDS_;     // 64 x LDS_  (also V)
    float* Ps   = Ks + 64 * LDS_;     // scores -> probs
    float* Os   = Ps + 64 * LDS_;     // output accumulator
    float* mrow = Os + 64 * LDS_;     // 64
    float* lrow = mrow + 64;          // 64
    float* arow = lrow + 64;          // 64
    float* red  = arow + 64;          // 4 x 64

    const int tid  = threadIdx.x;
    const int warp = tid >> 5;
    const int tr   = warp >> 1;
    const int tcb  = (warp & 1) * 2;
    const int qblk = blockIdx.x;              // 0..31
    const int bh   = blockIdx.y;              // 0..31
    const int b = bh >> 3, h = bh & 7;

    const float* qbase = g_q + (size_t)b * SS * DD + (size_t)h * HD;

    // Load Q tile, zero O, init m/l
#pragma unroll
    for (int i = tid; i < 1024; i += 256) {
        int r = i >> 4, c4 = (i & 15) << 2;
        *(float4*)(Qs + r * LDS_ + c4) =
            *(const float4*)(qbase + (size_t)(qblk * 64 + r) * DD + c4);
        *(float4*)(Os + r * LDS_ + c4) = make_float4(0.f, 0.f, 0.f, 0.f);
    }
    if (tid < 64) { mrow[tid] = -1e30f; lrow[tid] = 0.f; }
    __syncthreads();

    for (int j = 0; j < SS / 64; j++) {
        // ---- load K/V tile ----
#pragma unroll
        for (int i = tid; i < 1024; i += 256) {
            int r = i >> 4, c4 = (i & 15) << 2;
            *(float4*)(Ks + r * LDS_ + c4) =
                *(const float4*)(qbase + (size_t)(j * 64 + r) * DD + c4);
        }
        __syncthreads();

        // ---- S = (Q K^T) / 8, 3xTF32 ----
        {
            wmma::fragment<wmma::accumulator, 16, 16, 8, float> s[2];
            wmma::fill_fragment(s[0], 0.f);
            wmma::fill_fragment(s[1], 0.f);
#pragma unroll
            for (int kk = 0; kk < 64; kk += 8) {
                wmma::fragment<wmma::matrix_a, 16, 16, 8, wmma::precision::tf32, wmma::row_major> ah, al;
                wmma::load_matrix_sync(ah, Qs + tr * 16 * LDS_ + kk, LDS_);
                tf32_split(ah, al);
#pragma unroll
                for (int t = 0; t < 2; t++) {
                    // B = K^T : col_major view of row-major K tile
                    wmma::fragment<wmma::matrix_b, 16, 16, 8, wmma::precision::tf32, wmma::col_major> bh_, bl_;
                    wmma::load_matrix_sync(bh_, Ks + (tcb + t) * 16 * LDS_ + kk, LDS_);
                    tf32_split(bh_, bl_);
                    wmma::mma_sync(s[t], ah, bh_, s[t]);
                    wmma::mma_sync(s[t], al, bh_, s[t]);
                    wmma::mma_sync(s[t], ah, bl_, s[t]);
                }
            }
#pragma unroll
            for (int t = 0; t < 2; t++) {
#pragma unroll
                for (int i = 0; i < s[t].num_elements; i++) s[t].x[i] *= 0.125f;
                wmma::store_matrix_sync(Ps + tr * 16 * LDS_ + (tcb + t) * 16, s[t],
                                        LDS_, wmma::mem_row_major);
            }
        }
        __syncthreads();

        // ---- online softmax: partial row max ----
        {
            const int r = tid & 63, seg = tid >> 6;
            const float* row = Ps + r * LDS_ + seg * 16;
            float mx = -1e30f;
#pragma unroll
            for (int c = 0; c < 16; c++) mx = fmaxf(mx, row[c]);
            red[seg * 64 + r] = mx;
        }
        __syncthreads();
        if (tid < 64) {
            float mn = mrow[tid];
            mn = fmaxf(mn, red[tid]);
            mn = fmaxf(mn, red[64 + tid]);
            mn = fmaxf(mn, red[128 + tid]);
            mn = fmaxf(mn, red[192 + tid]);
            float a = __expf(mrow[tid] - mn);
            arow[tid] = a;
            lrow[tid] *= a;
            mrow[tid] = mn;
        }
        __syncthreads();
        // ---- exp, partial row sum, rescale O ----
        {
            const int r = tid & 63, seg = tid >> 6;
            float* prow = Ps + r * LDS_ + seg * 16;
            float* orow = Os + r * LDS_ + seg * 16;
            const float mn = mrow[r];
            const float a  = arow[r];
            float ssum = 0.f;
#pragma unroll
            for (int c = 0; c < 16; c++) {
                float p = __expf(prow[c] - mn);
                prow[c] = p;
                ssum += p;
                orow[c] *= a;
            }
            red[seg * 64 + r] = ssum;
        }
        __syncthreads();
        if (tid < 64) {
            lrow[tid] += red[tid] + red[64 + tid] + red[128 + tid] + red[192 + tid];
        }

        // ---- O += P @ V, 3xTF32 (V = K tile, row-major) ----
        {
#pragma unroll
            for (int t = 0; t < 2; t++) {
                wmma::fragment<wmma::accumulator, 16, 16, 8, float> o;
                wmma::load_matrix_sync(o, Os + tr * 16 * LDS_ + (tcb + t) * 16,
                                       LDS_, wmma::mem_row_major);
#pragma unroll
                for (int kk = 0; kk < 64; kk += 8) {
                    wmma::fragment<wmma::matrix_a, 16, 16, 8, wmma::precision::tf32, wmma::row_major> ah, al;
                    wmma::load_matrix_sync(ah, Ps + tr * 16 * LDS_ + kk, LDS_);
                    tf32_split(ah, al);
                    wmma::fragment<wmma::matrix_b, 16, 16, 8, wmma::precision::tf32, wmma::row_major> bh_, bl_;
                    wmma::load_matrix_sync(bh_, Ks + kk * LDS_ + (tcb + t) * 16, LDS_);
                    tf32_split(bh_, bl_);
                    wmma::mma_sync(o, ah, bh_, o);
                    wmma::mma_sync(o, al, bh_, o);
                    wmma::mma_sync(o, ah, bl_, o);
                }
                wmma::store_matrix_sync(Os + tr * 16 * LDS_ + (tcb + t) * 16, o,
                                        LDS_, wmma::mem_row_major);
            }
        }
        __syncthreads();  // before next K tile overwrite
    }

    // ---- epilogue: out = O / l ----
    float* obase = out + (size_t)b * SS * DD + (size_t)h * HD;
#pragma unroll
    for (int i = tid; i < 1024; i += 256) {
        int r = i >> 4, c4 = (i & 15) << 2;
        float inv = 1.f / lrow[r];
        float4 v = *(float4*)(Os + r * LDS_ + c4);
        v.x *= inv; v.y *= inv; v.z *= inv; v.w *= inv;
        *(float4*)(obase + (size_t)(qblk * 64 + r) * DD + c4) = v;
    }
}

static const int ATTN_SMEM = (4 * 64 * LDS_ + 3 * 64 + 4 * 64) * (int)sizeof(float);  // 75520 B

extern "C" void kernel_launch(void* const* d_in, const int* in_sizes, int n_in,
                              void* d_out, int out_size) {
    const float* x  = (const float*)d_in[0];
    const float* Wq = (const float*)d_in[1];
    float* out = (float*)d_out;

    cudaFuncSetAttribute(attn_kernel, cudaFuncAttributeMaxDynamicSharedMemorySize, ATTN_SMEM);

    qproj_kernel<<<dim3(128, 8), 256>>>(x, Wq);
    attn_kernel<<<dim3(SS / 64, BB * HH), 256, ATTN_SMEM>>>(out);
}

// round 4
// speedup vs baseline: 3.5722x; 3.5722x over previous
#include <cuda_runtime.h>
#include <cuda_fp16.h>
#include <mma.h>
#include <cstdint>

using namespace nvcuda;

#define BB 4
#define SS 2048
#define DD 512
#define HH 8
#define HD 64
#define LDH 72   // half leading dim for 64-wide tiles
#define LDF 68   // float leading dim

// q = x @ Wq, pre-split into fp16 hi/lo pairs (packed half2 per uint32)
__device__ uint32_t g_qh[(size_t)BB * SS * DD / 2];
__device__ uint32_t g_ql[(size_t)BB * SS * DD / 2];

__device__ __forceinline__ float f16hi(float v) {
    return __half2float(__float2half_rn(v));
}
__device__ __forceinline__ uint32_t packh2(float a, float b) {
    __half2 h = __floats2half2_rn(a, b);
    return *(uint32_t*)&h;
}

// ---------------------------------------------------------------------------
// Kernel 1: q = x @ Wq  via fp16 wmma, 3-term split (hi,lo).
// Writes pre-split packed fp16 arrays g_qh / g_ql.
// ---------------------------------------------------------------------------
__global__ __launch_bounds__(256) void qproj_kernel(const float* __restrict__ x,
                                                    const float* __restrict__ w) {
    __shared__ __align__(16) __half Ah[64 * LDH];
    __shared__ __align__(16) __half Al[64 * LDH];
    __shared__ __align__(16) __half Bh[64 * LDH];
    __shared__ __align__(16) __half Bl[64 * LDH];

    const int tid  = threadIdx.x;
    const int warp = tid >> 5;
    const int tr   = warp >> 1;        // 0..3
    const int tcb  = (warp & 1) * 2;   // 0 or 2
    const int bm   = blockIdx.x;       // 0..127
    const int bn   = blockIdx.y;       // 0..7

    wmma::fragment<wmma::accumulator, 16, 16, 16, float> c[2];
    wmma::fill_fragment(c[0], 0.f);
    wmma::fill_fragment(c[1], 0.f);

    const float* xbase = x + (size_t)bm * 64 * DD;

    for (int k0 = 0; k0 < DD; k0 += 64) {
#pragma unroll
        for (int i = tid; i < 1024; i += 256) {
            int rr = i >> 4, c4 = (i & 15) << 2;
            float4 a = *(const float4*)(xbase + (size_t)rr * DD + k0 + c4);
            float4 b = *(const float4*)(w + (size_t)(k0 + rr) * DD + bn * 64 + c4);
            uint32_t* Ahp = (uint32_t*)(Ah + rr * LDH + c4);
            uint32_t* Alp = (uint32_t*)(Al + rr * LDH + c4);
            uint32_t* Bhp = (uint32_t*)(Bh + rr * LDH + c4);
            uint32_t* Blp = (uint32_t*)(Bl + rr * LDH + c4);
            Ahp[0] = packh2(a.x, a.y);
            Ahp[1] = packh2(a.z, a.w);
            Alp[0] = packh2(a.x - f16hi(a.x), a.y - f16hi(a.y));
            Alp[1] = packh2(a.z - f16hi(a.z), a.w - f16hi(a.w));
            Bhp[0] = packh2(b.x, b.y);
            Bhp[1] = packh2(b.z, b.w);
            Blp[0] = packh2(b.x - f16hi(b.x), b.y - f16hi(b.y));
            Blp[1] = packh2(b.z - f16hi(b.z), b.w - f16hi(b.w));
        }
        __syncthreads();

#pragma unroll
        for (int kk = 0; kk < 64; kk += 16) {
            wmma::fragment<wmma::matrix_a, 16, 16, 16, __half, wmma::row_major> a_h, a_l;
            wmma::load_matrix_sync(a_h, Ah + tr * 16 * LDH + kk, LDH);
            wmma::load_matrix_sync(a_l, Al + tr * 16 * LDH + kk, LDH);
#pragma unroll
            for (int t = 0; t < 2; t++) {
                wmma::fragment<wmma::matrix_b, 16, 16, 16, __half, wmma::row_major> b_h, b_l;
                wmma::load_matrix_sync(b_h, Bh + kk * LDH + (tcb + t) * 16, LDH);
                wmma::load_matrix_sync(b_l, Bl + kk * LDH + (tcb + t) * 16, LDH);
                wmma::mma_sync(c[t], a_h, b_h, c[t]);
                wmma::mma_sync(c[t], a_l, b_h, c[t]);
                wmma::mma_sync(c[t], a_h, b_l, c[t]);
            }
        }
        __syncthreads();
    }

    // Write C via SMEM (reuse Ah/Al as fp32 buffer), split to fp16 hi/lo.
    float* Cs = (float*)Ah;  // 64 x LDF floats = 17408 B (< 18432 B of Ah+Al)
#pragma unroll
    for (int t = 0; t < 2; t++)
        wmma::store_matrix_sync(Cs + tr * 16 * LDF + (tcb + t) * 16, c[t], LDF, wmma::mem_row_major);
    __syncthreads();

#pragma unroll
    for (int i = tid; i < 2048; i += 256) {
        int rr = i >> 5, wv = i & 31;
        float c0 = Cs[rr * LDF + 2 * wv];
        float c1 = Cs[rr * LDF + 2 * wv + 1];
        size_t word = (size_t)(bm * 64 + rr) * (DD / 2) + bn * 32 + wv;
        g_qh[word] = packh2(c0, c1);
        g_ql[word] = packh2(c0 - f16hi(c0), c1 - f16hi(c1));
    }
}

// ---------------------------------------------------------------------------
// Kernel 2: flash attention, Q=K=V, fp16 wmma 3-term split.
// Static per-row shift m_i = 0.125*|q_i|^2 (the diag score): softmax-invariant,
// constant across K tiles -> O accumulates unnormalized in registers.
// p = exp(s*0.125 - m_i) bounded ~e^6.3, fp16-safe.
// ---------------------------------------------------------------------------
// Dynamic SMEM byte offsets
#define OQH  0u
#define OQL  9216u
#define OKH  18432u
#define OKL  27648u
#define OPH  36864u
#define OPL  46080u
#define OPS  55296u                       // fp32 64 x LDF = 17408 B
#define OLR  72704u                       // lrow: 64 f32
#define ORED 72960u                       // red: 4 x 64 f32
#define OMR  73984u                       // mrow: 64 f32
#define ATTN_SMEM_BYTES 74240

__global__ __launch_bounds__(256) void attn_kernel(float* __restrict__ out) {
    extern __shared__ __align__(16) char dsm[];
    __half* Qh = (__half*)(dsm + OQH);
    __half* Ql = (__half*)(dsm + OQL);
    __half* Kh = (__half*)(dsm + OKH);
    __half* Kl = (__half*)(dsm + OKL);
    __half* Ph = (__half*)(dsm + OPH);
    __half* Pl = (__half*)(dsm + OPL);
    float*  Ps = (float*)(dsm + OPS);
    float*  lrow = (float*)(dsm + OLR);
    float*  red  = (float*)(dsm + ORED);
    float*  mrow = (float*)(dsm + OMR);

    const int tid  = threadIdx.x;
    const int warp = tid >> 5;
    const int tr   = warp >> 1;
    const int tcb  = (warp & 1) * 2;
    const int qblk = blockIdx.x;              // 0..31
    const int bh   = blockIdx.y;              // 0..31
    const int b = bh >> 3, h = bh & 7;

    const uint4* gqh = (const uint4*)g_qh;    // 64 uint4 per row
    const uint4* gql = (const uint4*)g_ql;

    // ---- load Q tile (64 x 64 halves, pre-split) ----
#pragma unroll
    for (int i = tid; i < 512; i += 256) {
        int r = i >> 3, c = i & 7;
        size_t idx = (size_t)(b * SS + qblk * 64 + r) * 64 + h * 8 + c;
        *(uint4*)(Qh + r * LDH + c * 8) = gqh[idx];
        *(uint4*)(Ql + r * LDH + c * 8) = gql[idx];
    }
    __syncthreads();
    // per-row static shift: m_i = 0.125 * |q_i|^2
    if (tid < 64) {
        float n2 = 0.f;
#pragma unroll
        for (int c = 0; c < 64; c++) {
            float v = __half2float(Qh[tid * LDH + c]) + __half2float(Ql[tid * LDH + c]);
            n2 = fmaf(v, v, n2);
        }
        mrow[tid] = 0.125f * n2;
        lrow[tid] = 0.f;
    }

    // persistent O accumulators
    wmma::fragment<wmma::accumulator, 16, 16, 16, float> o[2];
    wmma::fill_fragment(o[0], 0.f);
    wmma::fill_fragment(o[1], 0.f);

    for (int j = 0; j < SS / 64; j++) {
        __syncthreads();  // prev PV reads of Kh/Kl done; mrow/lrow visible (j=0)

        // ---- load K/V tile ----
#pragma unroll
        for (int i = tid; i < 512; i += 256) {
            int r = i >> 3, c = i & 7;
            size_t idx = (size_t)(b * SS + j * 64 + r) * 64 + h * 8 + c;
            *(uint4*)(Kh + r * LDH + c * 8) = gqh[idx];
            *(uint4*)(Kl + r * LDH + c * 8) = gql[idx];
        }
        __syncthreads();

        // ---- S = Q K^T (3-term fp16), store raw scores fp32 ----
        {
            wmma::fragment<wmma::accumulator, 16, 16, 16, float> s[2];
            wmma::fill_fragment(s[0], 0.f);
            wmma::fill_fragment(s[1], 0.f);
#pragma unroll
            for (int kk = 0; kk < 64; kk += 16) {
                wmma::fragment<wmma::matrix_a, 16, 16, 16, __half, wmma::row_major> a_h, a_l;
                wmma::load_matrix_sync(a_h, Qh + tr * 16 * LDH + kk, LDH);
                wmma::load_matrix_sync(a_l, Ql + tr * 16 * LDH + kk, LDH);
#pragma unroll
                for (int t = 0; t < 2; t++) {
                    wmma::fragment<wmma::matrix_b, 16, 16, 16, __half, wmma::col_major> b_h, b_l;
                    wmma::load_matrix_sync(b_h, Kh + (tcb + t) * 16 * LDH + kk, LDH);
                    wmma::load_matrix_sync(b_l, Kl + (tcb + t) * 16 * LDH + kk, LDH);
                    wmma::mma_sync(s[t], a_h, b_h, s[t]);
                    wmma::mma_sync(s[t], a_l, b_h, s[t]);
                    wmma::mma_sync(s[t], a_h, b_l, s[t]);
                }
            }
#pragma unroll
            for (int t = 0; t < 2; t++)
                wmma::store_matrix_sync(Ps + tr * 16 * LDF + (tcb + t) * 16, s[t],
                                        LDF, wmma::mem_row_major);
        }
        __syncthreads();

        // ---- exp with per-row shift, split P to fp16 hi/lo, partial row sums ----
        {
            const int r = tid & 63, seg = tid >> 6;
            const float m = mrow[r];
            const float* prow = Ps + r * LDF + seg * 16;
            uint32_t* ph = (uint32_t*)(Ph + r * LDH + seg * 16);
            uint32_t* pl = (uint32_t*)(Pl + r * LDH + seg * 16);
            float ssum = 0.f;
#pragma unroll
            for (int k = 0; k < 8; k++) {
                float p0 = __expf(fmaf(prow[2 * k],     0.125f, -m));
                float p1 = __expf(fmaf(prow[2 * k + 1], 0.125f, -m));
                ssum += p0 + p1;
                ph[k] = packh2(p0, p1);
                pl[k] = packh2(p0 - f16hi(p0), p1 - f16hi(p1));
            }
            red[seg * 64 + r] = ssum;
        }
        __syncthreads();
        if (tid < 64)
            lrow[tid] += red[tid] + red[64 + tid] + red[128 + tid] + red[192 + tid];

        // ---- O += P V (3-term fp16), V = K tile row-major ----
#pragma unroll
        for (int kk = 0; kk < 64; kk += 16) {
            wmma::fragment<wmma::matrix_a, 16, 16, 16, __half, wmma::row_major> a_h, a_l;
            wmma::load_matrix_sync(a_h, Ph + tr * 16 * LDH + kk, LDH);
            wmma::load_matrix_sync(a_l, Pl + tr * 16 * LDH + kk, LDH);
#pragma unroll
            for (int t = 0; t < 2; t++) {
                wmma::fragment<wmma::matrix_b, 16, 16, 16, __half, wmma::row_major> b_h, b_l;
                wmma::load_matrix_sync(b_h, Kh + kk * LDH + (tcb + t) * 16, LDH);
                wmma::load_matrix_sync(b_l, Kl + kk * LDH + (tcb + t) * 16, LDH);
                wmma::mma_sync(o[t], a_h, b_h, o[t]);
                wmma::mma_sync(o[t], a_l, b_h, o[t]);
                wmma::mma_sync(o[t], a_h, b_l, o[t]);
            }
        }
    }

    // ---- epilogue: out = O / l ----
    __syncthreads();
#pragma unroll
    for (int t = 0; t < 2; t++)
        wmma::store_matrix_sync(Ps + tr * 16 * LDF + (tcb + t) * 16, o[t], LDF, wmma::mem_row_major);
    __syncthreads();

    float* obase = out + (size_t)b * SS * DD + (size_t)h * HD;
#pragma unroll
    for (int i = tid; i < 1024; i += 256) {
        int r = i >> 4, c4 = (i & 15) << 2;
        float inv = 1.f / lrow[r];
        float4 v = *(float4*)(Ps + r * LDF + c4);
        v.x *= inv; v.y *= inv; v.z *= inv; v.w *= inv;
        *(float4*)(obase + (size_t)(qblk * 64 + r) * DD + c4) = v;
    }
}

extern "C" void kernel_launch(void* const* d_in, const int* in_sizes, int n_in,
                              void* d_out, int out_size) {
    const float* x  = (const float*)d_in[0];
    const float* Wq = (const float*)d_in[1];
    float* out = (float*)d_out;

    cudaFuncSetAttribute(attn_kernel, cudaFuncAttributeMaxDynamicSharedMemorySize, ATTN_SMEM_BYTES);

    qproj_kernel<<<dim3(128, 8), 256>>>(x, Wq);
    attn_kernel<<<dim3(SS / 64, BB * HH), 256, ATTN_SMEM_BYTES>>>(out);
}